// round 14
// baseline (speedup 1.0000x reference)
#include <cuda_runtime.h>
#include <cstdint>

// MultiLevelEmbedding: out[b,t,:] = emb_tables[level_ids[b,t], token_ids[b,t], :]
//                                   + level_embed[level_ids[b,t], :]
// B=64, T=1024, L=4, VOCAB=258, D=512 (float32).
//
// R14 = R13 (chunk-split warps: warp owns a fixed 128B column chunk of 8
// consecutive rows; only 4 level_embed float4 in registers) with the index
// path fixed: lanes 0-7 load the 8 (level,token) pairs lane-parallel
// (2 LDG wavefronts instead of 16 broadcast LDGs) and precompute
// rowoff = l*VOCAB+t; per row the warp reads rowoff/l via __shfl_sync
// (SHFL pipe, off L1tex). Data path per row-chunk stays 1 LDG.128 +
// FSEL-add + 1 STG.128 = pure-gather wavefront count (~24.5 us wall).
// Index dtype (int64 vs int32) via per-warp ballot on odd 32-bit words of
// token_ids (values < 258 => odd words all-zero iff int64; P(false) ~ 0).

#define D_VEC     128                 // float4 per row (D=512)
#define VOCAB_SZ  258
#define N_POS     (64 * 1024)         // B*T rows
#define ROWS_PW   8                   // rows per warp (per chunk)
#define FULL      0xffffffffu

#define SEL_ADD(dst, A, L)                                             \
    do {                                                               \
        float4 _b;                                                     \
        _b.x = (L)==0 ? b0.x : (L)==1 ? b1.x : (L)==2 ? b2.x : b3.x;   \
        _b.y = (L)==0 ? b0.y : (L)==1 ? b1.y : (L)==2 ? b2.y : b3.y;   \
        _b.z = (L)==0 ? b0.z : (L)==1 ? b1.z : (L)==2 ? b2.z : b3.z;   \
        _b.w = (L)==0 ? b0.w : (L)==1 ? b1.w : (L)==2 ? b2.w : b3.w;   \
        (dst).x = (A).x + _b.x; (dst).y = (A).y + _b.y;                \
        (dst).z = (A).z + _b.z; (dst).w = (A).w + _b.w;                \
    } while (0)

__global__ __launch_bounds__(256)
void mle_kernel(const void* __restrict__ level_ids_raw,
                const void* __restrict__ token_ids_raw,
                const float4* __restrict__ emb_tables,
                const float4* __restrict__ level_embed,
                float4* __restrict__ out) {
    const int lane  = threadIdx.x & 31;
    const int warp  = (blockIdx.x * 256 + threadIdx.x) >> 5;  // 0..32767
    const int chunk = warp & 3;                // which 32-float4 chunk
    const int rbase = (warp >> 2) * ROWS_PW;   // first row of this group
    const int cofs  = chunk * 32 + lane;       // column (float4 units)

    // ---- dtype detection (1 LDG + ballot, warp-uniform) ----
    const uint32_t* tr = (const uint32_t*)token_ids_raw;
    const unsigned nz  = __ballot_sync(FULL, tr[2 * lane + 1] != 0u);
    const bool is64    = (nz == 0u);

    // ---- this chunk's level_embed values for all 4 levels (16 regs) ----
    const float4 b0 = __ldg(level_embed + 0 * D_VEC + cofs);
    const float4 b1 = __ldg(level_embed + 1 * D_VEC + cofs);
    const float4 b2 = __ldg(level_embed + 2 * D_VEC + cofs);
    const float4 b3 = __ldg(level_embed + 3 * D_VEC + cofs);

    // ---- lane-parallel index fetch: lanes 0-7 own one row each ----
    int lv = 0, ro = 0;                // level, row offset (lanes 0-7)
    if (lane < ROWS_PW) {
        const int p = rbase + lane;
        int tv;
        if (is64) {
            lv = (int)((const long long*)level_ids_raw)[p];
            tv = (int)((const long long*)token_ids_raw)[p];
        } else {
            lv = ((const int*)level_ids_raw)[p];
            tv = ((const int*)token_ids_raw)[p];
        }
        ro = lv * VOCAB_SZ + tv;
    }

    #pragma unroll
    for (int r = 0; r < ROWS_PW; r += 4) {
        // broadcast row offsets + levels from owning lanes (SHFL pipe)
        const int ro0 = __shfl_sync(FULL, ro, r);
        const int ro1 = __shfl_sync(FULL, ro, r + 1);
        const int ro2 = __shfl_sync(FULL, ro, r + 2);
        const int ro3 = __shfl_sync(FULL, ro, r + 3);
        const int l0  = __shfl_sync(FULL, lv, r);
        const int l1  = __shfl_sync(FULL, lv, r + 1);
        const int l2  = __shfl_sync(FULL, lv, r + 2);
        const int l3  = __shfl_sync(FULL, lv, r + 3);

        // 4 independent table loads in flight (128B coalesced each)
        const float4 a0 = __ldg(emb_tables + (long long)ro0 * D_VEC + cofs);
        const float4 a1 = __ldg(emb_tables + (long long)ro1 * D_VEC + cofs);
        const float4 a2 = __ldg(emb_tables + (long long)ro2 * D_VEC + cofs);
        const float4 a3 = __ldg(emb_tables + (long long)ro3 * D_VEC + cofs);

        float4 r0, r1, r2, r3;
        SEL_ADD(r0, a0, l0);
        SEL_ADD(r1, a1, l1);
        SEL_ADD(r2, a2, l2);
        SEL_ADD(r3, a3, l3);

        const long long p0 = rbase + r;
        __stcs(out + (p0    ) * D_VEC + cofs, r0);
        __stcs(out + (p0 + 1) * D_VEC + cofs, r1);
        __stcs(out + (p0 + 2) * D_VEC + cofs, r2);
        __stcs(out + (p0 + 3) * D_VEC + cofs, r3);
    }
}

extern "C" void kernel_launch(void* const* d_in, const int* in_sizes, int n_in,
                              void* d_out, int out_size) {
    const void*   level_ids  = d_in[0];
    const void*   token_ids  = d_in[1];
    const float4* emb_tables = (const float4*)d_in[2];
    const float4* level_emb  = (const float4*)d_in[3];
    float4*       out        = (float4*)d_out;

    // 32768 warps (4 chunk-warps x 8192 row-groups) / 8 warps per block
    mle_kernel<<<4096, 256>>>(level_ids, token_ids,
                              emb_tables, level_emb, out);
}